// round 1
// baseline (speedup 1.0000x reference)
#include <cuda_runtime.h>
#include <cstdint>

#define T_TOK   32768
#define IN_DIM  2048
#define OUT_DIM 768
#define NEXP    64
#define RRANK   16
#define SCALING 2.0f

#define BM 128
#define BN 128
#define BK 32
#define NTHREADS 256
#define KT (IN_DIM / BK)                    /* 64  */
#define MAX_MTILES ((T_TOK / BM) + NEXP)    /* 320 */
#define NT (OUT_DIM / BN)                   /* 6   */

// SMEM strides (floats), chosen for conflict-free fragment reads:
//  A reads: addr = row*AS_STRIDE + k, lanes vary row=lane/4, k=lane%4  -> stride%32==4 -> unique banks
//  B reads: addr = k*BS_STRIDE + n,  lanes vary k=lane%4, n=lane/4    -> stride%32==8 -> unique banks
#define AS_STRIDE  36
#define BS_STRIDE  136
#define WAS_STRIDE 24
#define ASC_STRIDE 20
#define WBS_STRIDE 136

__device__ __forceinline__ uint32_t smem_u32(const void* p) {
    return (uint32_t)__cvta_generic_to_shared(p);
}

__device__ __forceinline__ void cp16(float* dst, const float* src, bool valid) {
    uint32_t d = smem_u32(dst);
    int sz = valid ? 16 : 0;   // sz=0 zero-fills destination, no source bytes read
    asm volatile("cp.async.cg.shared.global [%0], [%1], 16, %2;\n"
                 :: "r"(d), "l"(src), "r"(sz));
}

__device__ __forceinline__ void mma_tf32(float c[4], const uint32_t a[4],
                                         uint32_t b0, uint32_t b1) {
    asm volatile(
        "mma.sync.aligned.m16n8k8.row.col.f32.tf32.tf32.f32 "
        "{%0,%1,%2,%3}, {%4,%5,%6,%7}, {%8,%9}, {%0,%1,%2,%3};\n"
        : "+f"(c[0]), "+f"(c[1]), "+f"(c[2]), "+f"(c[3])
        : "r"(a[0]), "r"(a[1]), "r"(a[2]), "r"(a[3]), "r"(b0), "r"(b1));
}

__global__ __launch_bounds__(NTHREADS, 1)
void lora_moe_kernel(const float* __restrict__ x,
                     const int*   __restrict__ m_sizes,
                     const float* __restrict__ w_base,
                     const float* __restrict__ w_a,
                     const float* __restrict__ w_b,
                     float*       __restrict__ out) {
    extern __shared__ float sm[];
    float* As  = sm;                                  // 2 * 128*36  = 9216
    float* Bs  = As  + 2 * BM * AS_STRIDE;            // 2 * 32*136  = 8704
    float* Was = Bs  + 2 * BK * BS_STRIDE;            // 2 * 32*24   = 1536
    float* Asc = Was + 2 * BK * WAS_STRIDE;           // 128*20      = 2560
    float* Wbs = Asc + BM * ASC_STRIDE;               // 16*136      = 2176

    const int tid  = threadIdx.x;
    const int lane = tid & 31;
    const int warp = tid >> 5;
    const int wm   = warp & 3;   // 0..3  (m direction, 32 rows each)
    const int wn   = warp >> 2;  // 0..1  (n direction, 64 cols each)

    // ---- stage m_sizes into smem (avoid 64-deep dependent LDG chain) ----
    int* msz = (int*)Asc;  // Asc region is not touched until epilogue
    if (tid < NEXP) msz[tid] = m_sizes[tid];
    __syncthreads();

    // ---- tile scan: which (expert, row_start, m_len) does blockIdx.x own? ----
    int e = 0, row_start = 0, m_len = 0, found = 0;
    {
        const int mt = blockIdx.x;
        int acc_rows = 0, acc_tiles = 0;
        for (e = 0; e < NEXP; e++) {
            int m  = msz[e];
            int nt = (m + BM - 1) >> 7;
            if (mt < acc_tiles + nt) {
                int lt    = mt - acc_tiles;
                row_start = acc_rows + lt * BM;
                m_len     = min(BM, m - lt * BM);
                found     = 1;
                break;
            }
            acc_tiles += nt;
            acc_rows  += m;
        }
    }
    __syncthreads();   // everyone done reading msz before cp.async reuses region? (Asc safe anyway)
    if (!found) return;

    const int n0 = blockIdx.y * BN;

    const float* xg  = x      + (size_t)row_start * IN_DIM;
    const float* bg  = w_base + (size_t)e * IN_DIM * OUT_DIM + n0;
    const float* ag  = w_a    + (size_t)e * IN_DIM * RRANK;
    const float* wbg = w_b    + (size_t)e * RRANK  * OUT_DIM + n0;

    float acc[2][8][4];
    float aacc[2][2][4];
    #pragma unroll
    for (int i = 0; i < 2; i++)
        #pragma unroll
        for (int j = 0; j < 8; j++)
            #pragma unroll
            for (int q = 0; q < 4; q++) acc[i][j][q] = 0.f;
    #pragma unroll
    for (int i = 0; i < 2; i++)
        #pragma unroll
        for (int j = 0; j < 2; j++)
            #pragma unroll
            for (int q = 0; q < 4; q++) aacc[i][j][q] = 0.f;

    // ---- async tile loader ----
    auto load_tiles = [&](int kt, int stage) {
        float* AsS = As  + stage * BM * AS_STRIDE;
        float* BsS = Bs  + stage * BK * BS_STRIDE;
        float* WaS = Was + stage * BK * WAS_STRIDE;
        const int k0 = kt * BK;
        // A: 128 rows x 32 floats = 1024 x 16B chunks
        #pragma unroll
        for (int i = 0; i < 4; i++) {
            int q  = tid + i * NTHREADS;
            int r  = q >> 3;
            int kc = (q & 7) << 2;
            bool v = r < m_len;
            const float* src = v ? (xg + (size_t)r * IN_DIM + k0 + kc) : xg;
            cp16(AsS + r * AS_STRIDE + kc, src, v);
        }
        // B: 32 rows x 128 floats = 1024 x 16B chunks
        #pragma unroll
        for (int i = 0; i < 4; i++) {
            int q  = tid + i * NTHREADS;
            int r  = q >> 5;
            int nc = (q & 31) << 2;
            cp16(BsS + r * BS_STRIDE + nc, bg + (size_t)(k0 + r) * OUT_DIM + nc, true);
        }
        // w_a: 32 rows x 16 floats = 128 x 16B chunks
        if (tid < 128) {
            int r  = tid >> 2;
            int nc = (tid & 3) << 2;
            cp16(WaS + r * WAS_STRIDE + nc, ag + (size_t)(k0 + r) * RRANK + nc, true);
        }
        asm volatile("cp.async.commit_group;\n");
    };

    // ---- compute one BK stage ----
    const int mrow = wm * 32 + (lane >> 2);
    const int tig  = lane & 3;
    auto compute = [&](int stage) {
        float* AsS = As  + stage * BM * AS_STRIDE;
        float* BsS = Bs  + stage * BK * BS_STRIDE;
        float* WaS = Was + stage * BK * WAS_STRIDE;
        #pragma unroll
        for (int kk = 0; kk < 4; kk++) {
            const int kb = kk * 8 + tig;
            uint32_t a[2][4];
            #pragma unroll
            for (int mf = 0; mf < 2; mf++) {
                const float* ap = AsS + (mrow + mf * 16) * AS_STRIDE + kb;
                a[mf][0] = __float_as_uint(ap[0]);
                a[mf][1] = __float_as_uint(ap[8 * AS_STRIDE]);
                a[mf][2] = __float_as_uint(ap[4]);
                a[mf][3] = __float_as_uint(ap[8 * AS_STRIDE + 4]);
            }
            #pragma unroll
            for (int nf = 0; nf < 8; nf++) {
                const int col = wn * 64 + nf * 8 + (lane >> 2);
                uint32_t b0 = __float_as_uint(BsS[kb * BS_STRIDE + col]);
                uint32_t b1 = __float_as_uint(BsS[(kb + 4) * BS_STRIDE + col]);
                mma_tf32(acc[0][nf], a[0], b0, b1);
                mma_tf32(acc[1][nf], a[1], b0, b1);
            }
            if (wn == 0) {  // warp-uniform: these warps also accumulate a = x @ w_a
                #pragma unroll
                for (int nf = 0; nf < 2; nf++) {
                    const int col = nf * 8 + (lane >> 2);
                    uint32_t b0 = __float_as_uint(WaS[kb * WAS_STRIDE + col]);
                    uint32_t b1 = __float_as_uint(WaS[(kb + 4) * WAS_STRIDE + col]);
                    mma_tf32(aacc[0][nf], a[0], b0, b1);
                    mma_tf32(aacc[1][nf], a[1], b0, b1);
                }
            }
        }
    };

    // ---- main loop: double-buffered cp.async pipeline ----
    load_tiles(0, 0);
    #pragma unroll 1
    for (int kt = 0; kt < KT; kt++) {
        const int cur = kt & 1;
        if (kt + 1 < KT) {
            load_tiles(kt + 1, cur ^ 1);
            asm volatile("cp.async.wait_group 1;\n");
        } else {
            asm volatile("cp.async.wait_group 0;\n");
        }
        __syncthreads();
        compute(cur);
        __syncthreads();
    }

    // ---- LoRA epilogue: a*SCALING -> smem; add (a*SCALING) @ w_b into acc ----
    if (wn == 0) {
        const int r0 = wm * 32 + (lane >> 2);
        const int c0 = 2 * (lane & 3);
        #pragma unroll
        for (int mf = 0; mf < 2; mf++)
            #pragma unroll
            for (int nf = 0; nf < 2; nf++) {
                const int rr = r0 + mf * 16;
                const int cc = nf * 8 + c0;
                Asc[rr * ASC_STRIDE + cc]           = aacc[mf][nf][0] * SCALING;
                Asc[rr * ASC_STRIDE + cc + 1]       = aacc[mf][nf][1] * SCALING;
                Asc[(rr + 8) * ASC_STRIDE + cc]     = aacc[mf][nf][2] * SCALING;
                Asc[(rr + 8) * ASC_STRIDE + cc + 1] = aacc[mf][nf][3] * SCALING;
            }
    }
    // w_b tile: 16 x 128 floats = 512 x 16B chunks
    #pragma unroll
    for (int i = 0; i < 2; i++) {
        int q  = tid + i * NTHREADS;
        int r  = q >> 5;
        int nc = (q & 31) << 2;
        float4 v = *reinterpret_cast<const float4*>(wbg + (size_t)r * OUT_DIM + nc);
        *reinterpret_cast<float4*>(Wbs + r * WBS_STRIDE + nc) = v;
    }
    __syncthreads();

    #pragma unroll
    for (int kk = 0; kk < 2; kk++) {
        const int kb = kk * 8 + tig;
        uint32_t a[2][4];
        #pragma unroll
        for (int mf = 0; mf < 2; mf++) {
            const float* ap = Asc + (mrow + mf * 16) * ASC_STRIDE + kb;
            a[mf][0] = __float_as_uint(ap[0]);
            a[mf][1] = __float_as_uint(ap[8 * ASC_STRIDE]);
            a[mf][2] = __float_as_uint(ap[4]);
            a[mf][3] = __float_as_uint(ap[8 * ASC_STRIDE + 4]);
        }
        #pragma unroll
        for (int nf = 0; nf < 8; nf++) {
            const int col = wn * 64 + nf * 8 + (lane >> 2);
            uint32_t b0 = __float_as_uint(Wbs[kb * WBS_STRIDE + col]);
            uint32_t b1 = __float_as_uint(Wbs[(kb + 4) * WBS_STRIDE + col]);
            mma_tf32(acc[0][nf], a[0], b0, b1);
            mma_tf32(acc[1][nf], a[1], b0, b1);
        }
    }

    // ---- store ----
    float* og = out + (size_t)row_start * OUT_DIM + n0;
    const int r0s = wm * 32 + (lane >> 2);
    const int c0s = wn * 64 + 2 * (lane & 3);
    #pragma unroll
    for (int mf = 0; mf < 2; mf++) {
        const int r1 = r0s + mf * 16;
        #pragma unroll
        for (int nf = 0; nf < 8; nf++) {
            const int cc = c0s + nf * 8;
            if (r1 < m_len)
                *reinterpret_cast<float2*>(og + (size_t)r1 * OUT_DIM + cc) =
                    make_float2(acc[mf][nf][0], acc[mf][nf][1]);
            if (r1 + 8 < m_len)
                *reinterpret_cast<float2*>(og + (size_t)(r1 + 8) * OUT_DIM + cc) =
                    make_float2(acc[mf][nf][2], acc[mf][nf][3]);
        }
    }
}

extern "C" void kernel_launch(void* const* d_in, const int* in_sizes, int n_in,
                              void* d_out, int out_size) {
    const float* x      = (const float*)d_in[0];
    const int*   msz    = (const int*)  d_in[1];
    const float* w_base = (const float*)d_in[2];
    const float* w_a    = (const float*)d_in[3];
    const float* w_b    = (const float*)d_in[4];
    float*       out    = (float*)d_out;

    const int smem_bytes =
        (2 * BM * AS_STRIDE + 2 * BK * BS_STRIDE + 2 * BK * WAS_STRIDE +
         BM * ASC_STRIDE + RRANK * WBS_STRIDE) * (int)sizeof(float);  // 96768

    cudaFuncSetAttribute(lora_moe_kernel,
                         cudaFuncAttributeMaxDynamicSharedMemorySize, smem_bytes);

    dim3 grid(MAX_MTILES, NT);
    lora_moe_kernel<<<grid, NTHREADS, smem_bytes>>>(x, msz, w_base, w_a, w_b, out);
}

// round 3
// speedup vs baseline: 1.6217x; 1.6217x over previous
#include <cuda_runtime.h>
#include <cuda_fp16.h>
#include <cstdint>

#define T_TOK   32768
#define IN_DIM  2048
#define OUT_DIM 768
#define NEXP    64
#define RRANK   16
#define SCALING 2.0f

#define BM 128
#define BN 128
#define BK 32
#define KT 64                              /* IN_DIM / BK */
#define MAX_MTILES 320                     /* T/BM + E */
#define NT 6                               /* OUT / BN */
#define NTHREADS 256

// byte strides of smem tile rows (all multiples of 16 for ldmatrix)
#define SA  80    /* A: 40 halves/row; ldmatrix groups lane*5 mod 8 distinct */
#define SB  272   /* B: 136 halves/row; groups k*17 mod 8 distinct */
#define SWA 48    /* WA: 24 halves/row; groups 3k mod 8 distinct */

#define SM_A0  0
#define SM_A1  10240
#define SM_B0  20480
#define SM_B1  29184
#define SM_WA0 37888
#define SM_WA1 39424
#define SM_MSZ 40960
#define SMEM_TOTAL 41216

__device__ __forceinline__ uint32_t h2u(__half2 h) {
    return *reinterpret_cast<uint32_t*>(&h);
}

__device__ __forceinline__ void ldsm_x4(uint32_t* r, uint32_t addr) {
    asm volatile("ldmatrix.sync.aligned.m8n8.x4.shared.b16 {%0,%1,%2,%3}, [%4];"
                 : "=r"(r[0]), "=r"(r[1]), "=r"(r[2]), "=r"(r[3]) : "r"(addr));
}
__device__ __forceinline__ void ldsm_x4_t(uint32_t* r, uint32_t addr) {
    asm volatile("ldmatrix.sync.aligned.m8n8.x4.trans.shared.b16 {%0,%1,%2,%3}, [%4];"
                 : "=r"(r[0]), "=r"(r[1]), "=r"(r[2]), "=r"(r[3]) : "r"(addr));
}
__device__ __forceinline__ void ldsm_x2_t(uint32_t* r, uint32_t addr) {
    asm volatile("ldmatrix.sync.aligned.m8n8.x2.trans.shared.b16 {%0,%1}, [%2];"
                 : "=r"(r[0]), "=r"(r[1]) : "r"(addr));
}

__device__ __forceinline__ void mma_f16(float* c, const uint32_t* a,
                                        uint32_t b0, uint32_t b1) {
    asm volatile(
        "mma.sync.aligned.m16n8k16.row.col.f32.f16.f16.f32 "
        "{%0,%1,%2,%3},{%4,%5,%6,%7},{%8,%9},{%0,%1,%2,%3};"
        : "+f"(c[0]), "+f"(c[1]), "+f"(c[2]), "+f"(c[3])
        : "r"(a[0]), "r"(a[1]), "r"(a[2]), "r"(a[3]), "r"(b0), "r"(b1));
}

__global__ __launch_bounds__(NTHREADS, 2)
void lora_moe_h(const float* __restrict__ x,
                const int*   __restrict__ m_sizes,
                const float* __restrict__ w_base,
                const float* __restrict__ w_a,
                const float* __restrict__ w_b,
                float*       __restrict__ out) {
    __shared__ __align__(128) char smem[SMEM_TOTAL];
    const uint32_t sb = (uint32_t)__cvta_generic_to_shared(smem);

    const int tid  = threadIdx.x;
    const int lane = tid & 31;
    const int warp = tid >> 5;
    const int wm   = warp & 3;   // m quarter (32 rows)
    const int wn   = warp >> 2;  // n half (64 cols)

    // ---- stage m_sizes ----
    int* msz = (int*)(smem + SM_MSZ);
    if (tid < NEXP) msz[tid] = m_sizes[tid];
    __syncthreads();

    // ---- tile scan ----
    int e = 0, row_start = 0, m_len = 0, found = 0;
    {
        const int mt = blockIdx.x;
        int acc_rows = 0, acc_tiles = 0;
        for (e = 0; e < NEXP; e++) {
            int m  = msz[e];
            int nt = (m + BM - 1) >> 7;
            if (mt < acc_tiles + nt) {
                int lt    = mt - acc_tiles;
                row_start = acc_rows + lt * BM;
                m_len     = min(BM, m - lt * BM);
                found     = 1;
                break;
            }
            acc_tiles += nt;
            acc_rows  += m;
        }
    }
    if (!found) return;

    const int n0 = blockIdx.y * BN;
    const float* xg  = x      + (size_t)row_start * IN_DIM;
    const float* bg  = w_base + (size_t)e * IN_DIM * OUT_DIM + n0;
    const float* ag  = w_a    + (size_t)e * IN_DIM * RRANK;
    const float* wbg = w_b    + (size_t)e * RRANK  * OUT_DIM + n0;

    float acc[2][8][4];
    float aacc[2][4];
    #pragma unroll
    for (int i = 0; i < 2; i++) {
        #pragma unroll
        for (int j = 0; j < 8; j++)
            #pragma unroll
            for (int q = 0; q < 4; q++) acc[i][j][q] = 0.f;
        #pragma unroll
        for (int q = 0; q < 4; q++) aacc[i][q] = 0.f;
    }

    float4 fa[4], fb[4], fwa;

    // ---- global prefetch (fp32) ----
    auto load_regs = [&](int kt) {
        const int k0 = kt * BK;
        #pragma unroll
        for (int j = 0; j < 4; j++) {
            int idx = tid + j * NTHREADS;           // 0..1023
            int row = idx >> 3, kc = idx & 7;
            bool v = (row_start + row) < T_TOK;
            fa[j] = v ? *(const float4*)(xg + (size_t)row * IN_DIM + k0 + kc * 4)
                      : make_float4(0.f, 0.f, 0.f, 0.f);
        }
        #pragma unroll
        for (int j = 0; j < 4; j++) {
            int idx = tid + j * NTHREADS;
            int k = idx >> 5, nq = idx & 31;
            fb[j] = *(const float4*)(bg + (size_t)(k0 + k) * OUT_DIM + nq * 4);
        }
        if (tid < 128) {
            int k = tid >> 2, rq = tid & 3;
            fwa = *(const float4*)(ag + (size_t)(k0 + k) * RRANK + rq * 4);
        }
    };

    // ---- convert + store to smem (fp16) ----
    auto store_stage = [&](int st) {
        char* A  = smem + (st ? SM_A1  : SM_A0);
        char* B  = smem + (st ? SM_B1  : SM_B0);
        char* WA = smem + (st ? SM_WA1 : SM_WA0);
        #pragma unroll
        for (int j = 0; j < 4; j++) {
            int idx = tid + j * NTHREADS;
            int row = idx >> 3, kc = idx & 7;
            uint2 u;
            u.x = h2u(__floats2half2_rn(fa[j].x, fa[j].y));
            u.y = h2u(__floats2half2_rn(fa[j].z, fa[j].w));
            *(uint2*)(A + row * SA + kc * 8) = u;
        }
        #pragma unroll
        for (int j = 0; j < 4; j++) {
            int idx = tid + j * NTHREADS;
            int k = idx >> 5, nq = idx & 31;
            uint2 u;
            u.x = h2u(__floats2half2_rn(fb[j].x, fb[j].y));
            u.y = h2u(__floats2half2_rn(fb[j].z, fb[j].w));
            *(uint2*)(B + k * SB + nq * 8) = u;
        }
        if (tid < 128) {
            int k = tid >> 2, rq = tid & 3;
            uint2 u;
            u.x = h2u(__floats2half2_rn(fwa.x, fwa.y));
            u.y = h2u(__floats2half2_rn(fwa.z, fwa.w));
            *(uint2*)(WA + k * SWA + rq * 8) = u;
        }
    };

    // per-lane ldmatrix base offsets
    const uint32_t a_off  = (uint32_t)((wm * 32 + (lane & 15)) * SA + (lane >> 4) * 16);
    const uint32_t b_off  = (uint32_t)((lane & 15) * SB + (wn * 64 + (lane >> 4) * 8) * 2);
    const uint32_t wa_off = (uint32_t)((lane & 15) * SWA + wn * 16);

    auto compute = [&](int st) {
        const uint32_t Ab = sb + (st ? SM_A1  : SM_A0) + a_off;
        const uint32_t Bb = sb + (st ? SM_B1  : SM_B0) + b_off;
        const uint32_t Wb = sb + (st ? SM_WA1 : SM_WA0) + wa_off;
        #pragma unroll
        for (int ks = 0; ks < 2; ks++) {
            uint32_t am[2][4];
            ldsm_x4(am[0], Ab + ks * 32);
            ldsm_x4(am[1], Ab + ks * 32 + 16 * SA);
            uint32_t wf[2];
            ldsm_x2_t(wf, Wb + ks * 16 * SWA);
            #pragma unroll
            for (int p = 0; p < 4; p++) {
                uint32_t bf[4];
                ldsm_x4_t(bf, Bb + ks * 16 * SB + p * 32);
                mma_f16(acc[0][2 * p],     am[0], bf[0], bf[1]);
                mma_f16(acc[1][2 * p],     am[1], bf[0], bf[1]);
                mma_f16(acc[0][2 * p + 1], am[0], bf[2], bf[3]);
                mma_f16(acc[1][2 * p + 1], am[1], bf[2], bf[3]);
            }
            mma_f16(aacc[0], am[0], wf[0], wf[1]);
            mma_f16(aacc[1], am[1], wf[0], wf[1]);
        }
    };

    // ---- prologue ----
    load_regs(0);
    store_stage(0);
    __syncthreads();

    // ---- main loop ----
    #pragma unroll 1
    for (int kt = 0; kt < KT; kt++) {
        if (kt + 1 < KT) load_regs(kt + 1);   // LDG in flight during mma
        compute(kt & 1);
        __syncthreads();
        if (kt + 1 < KT) {
            store_stage((kt + 1) & 1);
            __syncthreads();
        }
    }
    __syncthreads();

    // ---- LoRA epilogue ----
    // a*SCALING -> Asc (reuse A0 buffer, same row stride), fp16 [row][r0..15]
    {
        char* Asc = smem + SM_A0;
        const int row0 = wm * 32 + (lane >> 2);
        const int cb   = wn * 8 + 2 * (lane & 3);
        #pragma unroll
        for (int mf = 0; mf < 2; mf++) {
            int r = row0 + mf * 16;
            *(uint32_t*)(Asc + r * SA + cb * 2) =
                h2u(__floats2half2_rn(aacc[mf][0] * SCALING, aacc[mf][1] * SCALING));
            *(uint32_t*)(Asc + (r + 8) * SA + cb * 2) =
                h2u(__floats2half2_rn(aacc[mf][2] * SCALING, aacc[mf][3] * SCALING));
        }
    }
    // w_b (16 x 128 fp32) -> Wbs (reuse B0 buffer) as fp16 [r][n]
    {
        char* Wbs = smem + SM_B0;
        #pragma unroll
        for (int j = 0; j < 2; j++) {
            int idx = tid + j * NTHREADS;       // 0..511
            int k = idx >> 5, nq = idx & 31;
            float4 f = *(const float4*)(wbg + (size_t)k * OUT_DIM + nq * 4);
            uint2 u;
            u.x = h2u(__floats2half2_rn(f.x, f.y));
            u.y = h2u(__floats2half2_rn(f.z, f.w));
            *(uint2*)(Wbs + k * SB + nq * 8) = u;
        }
    }
    __syncthreads();

    // (a*s) @ w_b, K=16, accumulate into acc
    {
        const int row = wm * 32 + (lane >> 2);
        uint32_t am[2][4];
        #pragma unroll
        for (int mf = 0; mf < 2; mf++) {
            const uint32_t base = sb + SM_A0 + (row + mf * 16) * SA + (lane & 3) * 4;
            asm volatile("ld.shared.b32 %0, [%1];" : "=r"(am[mf][0]) : "r"(base));
            asm volatile("ld.shared.b32 %0, [%1];" : "=r"(am[mf][1]) : "r"(base + 8 * SA));
            asm volatile("ld.shared.b32 %0, [%1];" : "=r"(am[mf][2]) : "r"(base + 16));
            asm volatile("ld.shared.b32 %0, [%1];" : "=r"(am[mf][3]) : "r"(base + 8 * SA + 16));
        }
        const uint32_t Bb = sb + SM_B0 + b_off;
        #pragma unroll
        for (int p = 0; p < 4; p++) {
            uint32_t bf[4];
            ldsm_x4_t(bf, Bb + p * 32);
            mma_f16(acc[0][2 * p],     am[0], bf[0], bf[1]);
            mma_f16(acc[1][2 * p],     am[1], bf[0], bf[1]);
            mma_f16(acc[0][2 * p + 1], am[0], bf[2], bf[3]);
            mma_f16(acc[1][2 * p + 1], am[1], bf[2], bf[3]);
        }
    }

    // ---- store ----
    {
        float* og = out + (size_t)row_start * OUT_DIM + n0;
        const int r0s = wm * 32 + (lane >> 2);
        const int c0s = wn * 64 + 2 * (lane & 3);
        #pragma unroll
        for (int mf = 0; mf < 2; mf++) {
            const int r1 = r0s + mf * 16;
            #pragma unroll
            for (int nf = 0; nf < 8; nf++) {
                const int cc = c0s + nf * 8;
                if (r1 < m_len)
                    *reinterpret_cast<float2*>(og + (size_t)r1 * OUT_DIM + cc) =
                        make_float2(acc[mf][nf][0], acc[mf][nf][1]);
                if (r1 + 8 < m_len)
                    *reinterpret_cast<float2*>(og + (size_t)(r1 + 8) * OUT_DIM + cc) =
                        make_float2(acc[mf][nf][2], acc[mf][nf][3]);
            }
        }
    }
}

extern "C" void kernel_launch(void* const* d_in, const int* in_sizes, int n_in,
                              void* d_out, int out_size) {
    const float* x      = (const float*)d_in[0];
    const int*   msz    = (const int*)  d_in[1];
    const float* w_base = (const float*)d_in[2];
    const float* w_a    = (const float*)d_in[3];
    const float* w_b    = (const float*)d_in[4];
    float*       out    = (float*)d_out;

    dim3 grid(MAX_MTILES, NT);
    lora_moe_h<<<grid, NTHREADS>>>(x, msz, w_base, w_a, w_b, out);
}

// round 4
// speedup vs baseline: 1.7475x; 1.0776x over previous
#include <cuda_runtime.h>
#include <cuda_fp16.h>
#include <cstdint>

#define T_TOK   32768
#define IN_DIM  2048
#define OUT_DIM 768
#define NEXP    64
#define RRANK   16
#define SCALING 2.0f

#define BM 128
#define BN 128
#define BK 64
#define KT2 (IN_DIM / BK)                  /* 32 */
#define MAX_MTILES 320
#define NT 6
#define NTHREADS 256

// smem row strides (bytes), conflict-free for ldmatrix (stride/16 odd)
#define SA  144   /* A: 64 halves + pad;  9r mod 8 distinct  */
#define SB  272   /* B: 128 halves + pad; 17k mod 8 distinct */
#define SWA 48    /* WA: 16 halves + pad; 3k mod 8 distinct  */

#define SM_A0   0
#define SM_A1   18432
#define SM_B0   36864
#define SM_B1   54272
#define SM_WA0  71680
#define SM_WA1  74752
#define SM_MSZ  77824
#define SMEM_BYTES 78336   /* 2 CTAs/SM: 2*78336 < 228KB */

// fp16 scratch (converted once per launch by prepass kernels)
__device__ __align__(16) __half g_xh [(size_t)T_TOK * IN_DIM];
__device__ __align__(16) __half g_wbh[(size_t)NEXP * IN_DIM * OUT_DIM];
__device__ __align__(16) __half g_wah[(size_t)NEXP * IN_DIM * RRANK];
__device__ __align__(16) __half g_wsh[(size_t)NEXP * RRANK * OUT_DIM];

__device__ __forceinline__ uint32_t h2u(__half2 h) {
    return *reinterpret_cast<uint32_t*>(&h);
}

__device__ __forceinline__ void cp16(uint32_t dst, const void* src, bool valid) {
    int sz = valid ? 16 : 0;   // sz=0 zero-fills, reads nothing
    asm volatile("cp.async.cg.shared.global [%0], [%1], 16, %2;\n"
                 :: "r"(dst), "l"(src), "r"(sz));
}

__device__ __forceinline__ void ldsm_x4(uint32_t* r, uint32_t addr) {
    asm volatile("ldmatrix.sync.aligned.m8n8.x4.shared.b16 {%0,%1,%2,%3}, [%4];"
                 : "=r"(r[0]), "=r"(r[1]), "=r"(r[2]), "=r"(r[3]) : "r"(addr));
}
__device__ __forceinline__ void ldsm_x4_t(uint32_t* r, uint32_t addr) {
    asm volatile("ldmatrix.sync.aligned.m8n8.x4.trans.shared.b16 {%0,%1,%2,%3}, [%4];"
                 : "=r"(r[0]), "=r"(r[1]), "=r"(r[2]), "=r"(r[3]) : "r"(addr));
}
__device__ __forceinline__ void ldsm_x2_t(uint32_t* r, uint32_t addr) {
    asm volatile("ldmatrix.sync.aligned.m8n8.x2.trans.shared.b16 {%0,%1}, [%2];"
                 : "=r"(r[0]), "=r"(r[1]) : "r"(addr));
}

__device__ __forceinline__ void mma_f16(float* c, const uint32_t* a,
                                        uint32_t b0, uint32_t b1) {
    asm volatile(
        "mma.sync.aligned.m16n8k16.row.col.f32.f16.f16.f32 "
        "{%0,%1,%2,%3},{%4,%5,%6,%7},{%8,%9},{%0,%1,%2,%3};"
        : "+f"(c[0]), "+f"(c[1]), "+f"(c[2]), "+f"(c[3])
        : "r"(a[0]), "r"(a[1]), "r"(a[2]), "r"(a[3]), "r"(b0), "r"(b1));
}

// ---- prepass: fp32 -> fp16, vectorized grid-stride ----
__global__ void __launch_bounds__(256)
cvt_kernel(const float4* __restrict__ src, uint2* __restrict__ dst, int n4) {
    int stride = gridDim.x * blockDim.x;
    for (int i = blockIdx.x * blockDim.x + threadIdx.x; i < n4; i += stride) {
        float4 f = src[i];
        uint2 u;
        u.x = h2u(__floats2half2_rn(f.x, f.y));
        u.y = h2u(__floats2half2_rn(f.z, f.w));
        dst[i] = u;
    }
}

__global__ __launch_bounds__(NTHREADS, 2)
void lora_moe_h2(const int* __restrict__ m_sizes, float* __restrict__ out) {
    extern __shared__ __align__(128) char smem[];
    const uint32_t sb = (uint32_t)__cvta_generic_to_shared(smem);

    const int tid  = threadIdx.x;
    const int lane = tid & 31;
    const int warp = tid >> 5;
    const int wm   = warp & 3;   // m quarter (32 rows)
    const int wn   = warp >> 2;  // n half (64 cols)

    int* msz = (int*)(smem + SM_MSZ);
    if (tid < NEXP) msz[tid] = m_sizes[tid];
    __syncthreads();

    // ---- tile scan ----
    int e = 0, row_start = 0, m_len = 0, found = 0;
    {
        const int mt = blockIdx.x;
        int acc_rows = 0, acc_tiles = 0;
        for (e = 0; e < NEXP; e++) {
            int m  = msz[e];
            int nt = (m + BM - 1) >> 7;
            if (mt < acc_tiles + nt) {
                int lt    = mt - acc_tiles;
                row_start = acc_rows + lt * BM;
                m_len     = min(BM, m - lt * BM);
                found     = 1;
                break;
            }
            acc_tiles += nt;
            acc_rows  += m;
        }
    }
    if (!found) return;

    const int n0 = blockIdx.y * BN;
    const __half* xg  = g_xh  + (size_t)row_start * IN_DIM;
    const __half* bg  = g_wbh + (size_t)e * IN_DIM * OUT_DIM + n0;
    const __half* ag  = g_wah + (size_t)e * IN_DIM * RRANK;
    const __half* wbg = g_wsh + (size_t)e * RRANK  * OUT_DIM + n0;

    float acc[2][8][4];
    float aacc[2][4];
    #pragma unroll
    for (int i = 0; i < 2; i++) {
        #pragma unroll
        for (int j = 0; j < 8; j++)
            #pragma unroll
            for (int q = 0; q < 4; q++) acc[i][j][q] = 0.f;
        #pragma unroll
        for (int q = 0; q < 4; q++) aacc[i][q] = 0.f;
    }

    // ---- async stage loader (all fp16 srcs) ----
    auto load_stage = [&](int kt) {
        const int st = kt & 1;
        const uint32_t A  = sb + (st ? SM_A1  : SM_A0);
        const uint32_t B  = sb + (st ? SM_B1  : SM_B0);
        const uint32_t WA = sb + (st ? SM_WA1 : SM_WA0);
        const int k0 = kt * BK;
        // A: 128 rows x 64 halves = 1024 x 16B
        #pragma unroll
        for (int j = 0; j < 4; j++) {
            int idx = tid + j * NTHREADS;
            int row = idx >> 3, kc = idx & 7;
            bool v = (row_start + row) < T_TOK;
            cp16(A + row * SA + kc * 16, xg + (size_t)row * IN_DIM + k0 + kc * 8, v);
        }
        // B: 64 rows x 128 halves = 1024 x 16B
        #pragma unroll
        for (int j = 0; j < 4; j++) {
            int idx = tid + j * NTHREADS;
            int k = idx >> 4, nq = idx & 15;
            cp16(B + k * SB + nq * 16, bg + (size_t)(k0 + k) * OUT_DIM + nq * 8, true);
        }
        // WA: 64 rows x 16 halves = 128 x 16B
        if (tid < 128) {
            int k = tid >> 1, rq = tid & 1;
            cp16(WA + k * SWA + rq * 16, ag + (size_t)(k0 + k) * RRANK + rq * 8, true);
        }
        asm volatile("cp.async.commit_group;\n");
    };

    // per-lane ldmatrix base offsets
    const uint32_t a_off  = (uint32_t)((wm * 32 + (lane & 15)) * SA + (lane >> 4) * 16);
    const uint32_t b_off  = (uint32_t)((lane & 15) * SB + (wn * 64 + (lane >> 4) * 8) * 2);
    const uint32_t wa_off = (uint32_t)((lane & 15) * SWA + wn * 16);

    auto compute = [&](int st) {
        const uint32_t Ab = sb + (st ? SM_A1  : SM_A0) + a_off;
        const uint32_t Bb = sb + (st ? SM_B1  : SM_B0) + b_off;
        const uint32_t Wb = sb + (st ? SM_WA1 : SM_WA0) + wa_off;
        #pragma unroll
        for (int ks = 0; ks < 4; ks++) {   // 4 x K=16
            uint32_t am[2][4];
            ldsm_x4(am[0], Ab + ks * 32);
            ldsm_x4(am[1], Ab + ks * 32 + 16 * SA);
            uint32_t wf[2];
            ldsm_x2_t(wf, Wb + ks * 16 * SWA);
            #pragma unroll
            for (int p = 0; p < 4; p++) {
                uint32_t bf[4];
                ldsm_x4_t(bf, Bb + ks * 16 * SB + p * 32);
                mma_f16(acc[0][2 * p],     am[0], bf[0], bf[1]);
                mma_f16(acc[1][2 * p],     am[1], bf[0], bf[1]);
                mma_f16(acc[0][2 * p + 1], am[0], bf[2], bf[3]);
                mma_f16(acc[1][2 * p + 1], am[1], bf[2], bf[3]);
            }
            mma_f16(aacc[0], am[0], wf[0], wf[1]);
            mma_f16(aacc[1], am[1], wf[0], wf[1]);
        }
    };

    // ---- pipeline ----
    load_stage(0);
    #pragma unroll 1
    for (int kt = 0; kt < KT2; kt++) {
        if (kt + 1 < KT2) {
            load_stage(kt + 1);
            asm volatile("cp.async.wait_group 1;\n");
        } else {
            asm volatile("cp.async.wait_group 0;\n");
        }
        __syncthreads();
        compute(kt & 1);
        __syncthreads();
    }

    // ---- LoRA epilogue: a*SCALING -> A0 (fp16), w_b -> B0, K=16 mma ----
    {
        char* Asc = smem + SM_A0;
        const int row0 = wm * 32 + (lane >> 2);
        const int cb   = wn * 8 + 2 * (lane & 3);
        #pragma unroll
        for (int mf = 0; mf < 2; mf++) {
            int r = row0 + mf * 16;
            *(uint32_t*)(Asc + r * SA + cb * 2) =
                h2u(__floats2half2_rn(aacc[mf][0] * SCALING, aacc[mf][1] * SCALING));
            *(uint32_t*)(Asc + (r + 8) * SA + cb * 2) =
                h2u(__floats2half2_rn(aacc[mf][2] * SCALING, aacc[mf][3] * SCALING));
        }
    }
    {
        // w_b fp16: 16 rows x 128 halves = 256 x 16B
        char* Wbs = smem + SM_B0;
        int k = tid >> 4, nq = tid & 15;
        uint4 v = *(const uint4*)(wbg + (size_t)k * OUT_DIM + nq * 8);
        *(uint4*)(Wbs + k * SB + nq * 16) = v;
    }
    __syncthreads();

    {
        const int row = wm * 32 + (lane >> 2);
        uint32_t am[2][4];
        #pragma unroll
        for (int mf = 0; mf < 2; mf++) {
            const uint32_t base = sb + SM_A0 + (row + mf * 16) * SA + (lane & 3) * 4;
            asm volatile("ld.shared.b32 %0, [%1];" : "=r"(am[mf][0]) : "r"(base));
            asm volatile("ld.shared.b32 %0, [%1];" : "=r"(am[mf][1]) : "r"(base + 8 * SA));
            asm volatile("ld.shared.b32 %0, [%1];" : "=r"(am[mf][2]) : "r"(base + 16));
            asm volatile("ld.shared.b32 %0, [%1];" : "=r"(am[mf][3]) : "r"(base + 8 * SA + 16));
        }
        const uint32_t Bb = sb + SM_B0 + b_off;
        #pragma unroll
        for (int p = 0; p < 4; p++) {
            uint32_t bf[4];
            ldsm_x4_t(bf, Bb + p * 32);
            mma_f16(acc[0][2 * p],     am[0], bf[0], bf[1]);
            mma_f16(acc[1][2 * p],     am[1], bf[0], bf[1]);
            mma_f16(acc[0][2 * p + 1], am[0], bf[2], bf[3]);
            mma_f16(acc[1][2 * p + 1], am[1], bf[2], bf[3]);
        }
    }

    // ---- store ----
    {
        float* og = out + (size_t)row_start * OUT_DIM + n0;
        const int r0s = wm * 32 + (lane >> 2);
        const int c0s = wn * 64 + 2 * (lane & 3);
        #pragma unroll
        for (int mf = 0; mf < 2; mf++) {
            const int r1 = r0s + mf * 16;
            #pragma unroll
            for (int nf = 0; nf < 8; nf++) {
                const int cc = c0s + nf * 8;
                if (r1 < m_len)
                    *reinterpret_cast<float2*>(og + (size_t)r1 * OUT_DIM + cc) =
                        make_float2(acc[mf][nf][0], acc[mf][nf][1]);
                if (r1 + 8 < m_len)
                    *reinterpret_cast<float2*>(og + (size_t)(r1 + 8) * OUT_DIM + cc) =
                        make_float2(acc[mf][nf][2], acc[mf][nf][3]);
            }
        }
    }
}

extern "C" void kernel_launch(void* const* d_in, const int* in_sizes, int n_in,
                              void* d_out, int out_size) {
    const float* x      = (const float*)d_in[0];
    const int*   msz    = (const int*)  d_in[1];
    const float* w_base = (const float*)d_in[2];
    const float* w_a    = (const float*)d_in[3];
    const float* w_b    = (const float*)d_in[4];
    float*       out    = (float*)d_out;

    // resolve scratch symbol addresses (no allocation)
    static __half* p_xh = nullptr;
    static __half *p_wbh, *p_wah, *p_wsh;
    if (!p_xh) {
        cudaGetSymbolAddress((void**)&p_xh,  g_xh);
        cudaGetSymbolAddress((void**)&p_wbh, g_wbh);
        cudaGetSymbolAddress((void**)&p_wah, g_wah);
        cudaGetSymbolAddress((void**)&p_wsh, g_wsh);
    }

    // prepass conversions (in-stream ordering guarantees completion before GEMM)
    const int nx  = (int)((size_t)T_TOK * IN_DIM / 4);
    const int nwb = (int)((size_t)NEXP * IN_DIM * OUT_DIM / 4);
    const int nwa = (int)((size_t)NEXP * IN_DIM * RRANK / 4);
    const int nws = (int)((size_t)NEXP * RRANK * OUT_DIM / 4);
    cvt_kernel<<<4096, 256>>>((const float4*)x,      (uint2*)p_xh,  nx);
    cvt_kernel<<<4096, 256>>>((const float4*)w_base, (uint2*)p_wbh, nwb);
    cvt_kernel<<<1024, 256>>>((const float4*)w_a,    (uint2*)p_wah, nwa);
    cvt_kernel<<<512,  256>>>((const float4*)w_b,    (uint2*)p_wsh, nws);

    static int cfg_done = 0;
    if (!cfg_done) {
        cudaFuncSetAttribute(lora_moe_h2,
                             cudaFuncAttributeMaxDynamicSharedMemorySize, SMEM_BYTES);
        cfg_done = 1;
    }
    dim3 grid(MAX_MTILES, NT);
    lora_moe_h2<<<grid, NTHREADS, SMEM_BYTES>>>(msz, out);
}